// round 15
// baseline (speedup 1.0000x reference)
#include <cuda_runtime.h>
#include <math.h>
#include <stdint.h>

// Problem constants
#define BATCH 2
#define T_SEQ 2048
#define CDIM  1024
#define NH    16
#define HS    64
#define QKV_ELEMS (BATCH * NH * T_SEQ * HS)   // 4 M floats = 16 MB each

// -2/1024 * ln(10000)
#define ROPE_COEF (-0.017988211f)

// Scratch (device globals — no allocation allowed in kernel_launch)
__device__ float g_q[QKV_ELEMS];
__device__ float g_k[QKV_ELEMS];
__device__ float g_v[QKV_ELEMS];
__device__ float g_x[BATCH * T_SEQ * CDIM];   // tf32-rounded x
__device__ float g_w[3 * CDIM * CDIM];        // tf32-rounded Wq|Wk|Wv

__device__ __forceinline__ uint32_t f2tf32(float f) {
    uint32_t r;
    asm("cvt.rna.tf32.f32 %0, %1;" : "=r"(r) : "f"(f));
    return r;
}
__device__ __forceinline__ float f2tf32f(float f) {
    return __uint_as_float(f2tf32(f));
}

#define MMA_TF32(C, A0, A1, A2, A3, B0, B1)                                    \
    asm volatile(                                                              \
        "mma.sync.aligned.m16n8k8.row.col.f32.tf32.tf32.f32 "                  \
        "{%0,%1,%2,%3}, {%4,%5,%6,%7}, {%8,%9}, {%0,%1,%2,%3};"                \
        : "+f"((C)[0]), "+f"((C)[1]), "+f"((C)[2]), "+f"((C)[3])               \
        : "r"(A0), "r"(A1), "r"(A2), "r"(A3), "r"(B0), "r"(B1))

// ldmatrix x4: four 8-row x 16B matrices; per-lane row addresses.
__device__ __forceinline__ void ldsm4(uint32_t* r, const float* p) {
    uint32_t addr = (uint32_t)__cvta_generic_to_shared(p);
    asm volatile(
        "ldmatrix.sync.aligned.m8n8.x4.shared.b16 {%0,%1,%2,%3}, [%4];"
        : "=r"(r[0]), "=r"(r[1]), "=r"(r[2]), "=r"(r[3]) : "r"(addr));
}

// cp.async helpers
__device__ __forceinline__ void cpa16(float* dst, const float* src) {
    uint32_t d = (uint32_t)__cvta_generic_to_shared(dst);
    asm volatile("cp.async.cg.shared.global [%0], [%1], 16;" :: "r"(d), "l"(src));
}
__device__ __forceinline__ void cpa4(float* dst, const float* src) {
    uint32_t d = (uint32_t)__cvta_generic_to_shared(dst);
    asm volatile("cp.async.ca.shared.global [%0], [%1], 4;" :: "r"(d), "l"(src));
}
#define CP_COMMIT() asm volatile("cp.async.commit_group;" ::: "memory")
#define CP_WAIT0()  asm volatile("cp.async.wait_group 0;" ::: "memory")

// ---------------------------------------------------------------------------
// Kernel 0: pre-round x and W to RNA tf32 (hoists all input cvt out of GEMM).
// ---------------------------------------------------------------------------
#define NX4 (BATCH * T_SEQ * CDIM / 4)   // 1 M float4
#define NW4 (CDIM * CDIM / 4)            // 256 K float4 per matrix

__global__ __launch_bounds__(256) void cvt_inputs(
    const float* __restrict__ x,
    const float* __restrict__ Wq,
    const float* __restrict__ Wk,
    const float* __restrict__ Wv)
{
    const int total = NX4 + 3 * NW4;
    for (int idx = blockIdx.x * 256 + threadIdx.x; idx < total;
         idx += gridDim.x * 256) {
        const float4* src;
        float4* dst;
        if (idx < NX4) {
            src = (const float4*)x + idx;
            dst = (float4*)g_x + idx;
        } else {
            const int r = idx - NX4;
            const int w = r / NW4;
            const int o = r - w * NW4;
            const float* W = (w == 0) ? Wq : ((w == 1) ? Wk : Wv);
            src = (const float4*)W + o;
            dst = (float4*)g_w + (size_t)w * NW4 + o;
        }
        float4 v = *src;
        *dst = make_float4(f2tf32f(v.x), f2tf32f(v.y),
                           f2tf32f(v.z), f2tf32f(v.w));
    }
}

// ---------------------------------------------------------------------------
// Kernel A: out = x @ W^T via tf32 mma, cp.async 2-stage pipeline,
// fused RoPE epilogue, outputs tf32-rounded [B,H,T,HS].
// Block tile 128x128 (two heads), 8 warps of 32x64, BK=32.
// Grid: (8, 32, 3), Block: 256.  smem = 2*(128+128)*36*4 = 73728 B
// -> 2 blocks/SM (16 warps) to hide barrier + mma latency.
// ---------------------------------------------------------------------------
#define GBM 128
#define GBN 128
#define GBK 32
#define APITCH 36
#define GTILE (GBM * APITCH)   // floats per A (or B) stage buffer

__global__ __launch_bounds__(256, 2) void qkv_gemm_tf32()
{
    extern __shared__ float gsm[];
    float* As = gsm;                  // [2][GBM*APITCH]
    float* Bs = gsm + 2 * GTILE;      // [2][GBN*APITCH]

    const int z = blockIdx.z;
    const float* __restrict__ X = g_x;
    const float* __restrict__ W = g_w + (size_t)z * CDIM * CDIM;
    float* __restrict__ out = (z == 0) ? g_q : ((z == 1) ? g_k : g_v);

    const int m0 = blockIdx.y * GBM;
    const int n0 = blockIdx.x * GBN;

    const int tid  = threadIdx.x;
    const int warp = tid >> 5;
    const int lane = tid & 31;
    const int g    = lane >> 2;
    const int tg   = lane & 3;

    const int wm = warp >> 1;          // 0..3 (32-row tile)
    const int wn = warp & 1;           // 0..1 (64-col tile)

    // ldmatrix per-lane source rows/cols
    const int arow = wm * 32 + (lane & 7) + ((lane >> 3) & 1) * 8;
    const int acol = (lane >> 4) * 4;
    const int brow = wn * 64 + (lane & 7) + (lane >> 4) * 8;
    const int bcol = ((lane >> 3) & 1) * 4;

    // cp.async loader mapping: 1024 float4 per tile each for A and B
    const int lrow = tid >> 3;             // 0..31 base row (x4 iters -> 128)
    const int lc4  = (tid & 7) * 4;        // 0..28

    auto issue_tile = [&](int s) {
        float* A = As + (s & 1) * GTILE;
        float* B = Bs + (s & 1) * GTILE;
        const int kofs = s * GBK + lc4;
#pragma unroll
        for (int i = 0; i < 4; i++) {
            const int r = lrow + 32 * i;
            cpa16(&A[r * APITCH + lc4], X + (size_t)(m0 + r) * CDIM + kofs);
            cpa16(&B[r * APITCH + lc4], W + (size_t)(n0 + r) * CDIM + kofs);
        }
        CP_COMMIT();
    };

    float c[2][8][4];
#pragma unroll
    for (int mi = 0; mi < 2; mi++)
#pragma unroll
        for (int ni = 0; ni < 8; ni++)
#pragma unroll
            for (int r = 0; r < 4; r++) c[mi][ni][r] = 0.f;

    auto compute_stage = [&](int s) {
        const float* A = As + (s & 1) * GTILE;
        const float* B = Bs + (s & 1) * GTILE;
#pragma unroll
        for (int k8 = 0; k8 < GBK; k8 += 8) {
            uint32_t a[2][4], b[4][4];
            ldsm4(a[0], &A[arow * APITCH + acol + k8]);
            ldsm4(a[1], &A[(arow + 16) * APITCH + acol + k8]);
#pragma unroll
            for (int nn = 0; nn < 4; nn++)
                ldsm4(b[nn], &B[(brow + nn * 16) * APITCH + bcol + k8]);
            // data pre-rounded to tf32 by cvt_inputs — no cvt here
#pragma unroll
            for (int mi = 0; mi < 2; mi++)
#pragma unroll
                for (int nn = 0; nn < 4; nn++) {
                    MMA_TF32(c[mi][2 * nn],     a[mi][0], a[mi][1], a[mi][2],
                             a[mi][3], b[nn][0], b[nn][1]);
                    MMA_TF32(c[mi][2 * nn + 1], a[mi][0], a[mi][1], a[mi][2],
                             a[mi][3], b[nn][2], b[nn][3]);
                }
        }
    };

    const int stages = CDIM / GBK;   // 32

    issue_tile(0);
    CP_WAIT0();                      // stage 0 arrived
    __syncthreads();

    for (int s = 0; s < stages; s++) {
        // Prefetch s+1 into the idle buffer (last read during compute(s-1);
        // the barrier below guaranteed all warps finished it).
        if (s + 1 < stages) issue_tile(s + 1);
        compute_stage(s);
        if (s + 1 < stages) {
            CP_WAIT0();              // stage s+1 arrived
            __syncthreads();         // visible to all; buffer s%2 free
        }
    }

    // ---- epilogue: RoPE (z<2) + tf32-round + store [B,H,T,HS] ----
#pragma unroll
    for (int mi = 0; mi < 2; mi++) {
#pragma unroll
        for (int ni = 0; ni < 8; ni++) {
            const int dg = wn * 64 + ni * 8 + 2 * tg;    // 0..127
            const int h  = blockIdx.x * 2 + (dg >> 6);
            const int d  = dg & 63;
            float theta = 0.f;
            if (z < 2) theta = expf((float)(d >> 1) * ROPE_COEF);
#pragma unroll
            for (int half = 0; half < 2; half++) {
                const int m = m0 + wm * 32 + mi * 16 + g + half * 8;
                const int t = m & (T_SEQ - 1);
                const int b = m >> 11;
                const float v0 = c[mi][ni][half * 2 + 0];
                const float v1 = c[mi][ni][half * 2 + 1];
                const size_t base =
                    (((size_t)(b * NH + h) * T_SEQ) + t) * HS + d;
                if (z < 2) {
                    // fp32 Cody-Waite mod 2pi (fast-math-proof)
                    const float ang = (float)t * theta;
                    const float nq = floorf(ang * 0.15915494309f);
                    float r = fmaf(-nq, 6.28125f, ang);
                    r = fmaf(-nq, 1.9353072e-3f, r);
                    const float sn = __sinf(r);
                    const float cs = __cosf(r);
                    *(float2*)(out + base) =
                        make_float2(f2tf32f(v0 * cs - v1 * sn),
                                    f2tf32f(v1 * cs + v0 * sn));
                } else {
                    *(float2*)(out + base) =
                        make_float2(f2tf32f(v0), f2tf32f(v1));
                }
            }
        }
    }
}

// ---------------------------------------------------------------------------
// Kernel B: tf32 mma flash attention, cp.async double-buffered K/V (inputs
// pre-rounded to tf32), register-shuffle P transpose. One barrier per tile.
// (unchanged from R13)
// ---------------------------------------------------------------------------
#define FPAD 68
#define QT 128
#define TILE68 (64 * FPAD)

__global__ __launch_bounds__(256, 2) void flash_attn7(float* __restrict__ out)
{
    extern __shared__ float sm[];
    float* Qs = sm;                       // [128][68]  Qs[q][d]   (tf32)
    float* Kb = Qs + QT * FPAD;           // [2][64][68] keys row-major
    float* Vb = Kb + 2 * TILE68;          // [2][64][68] Vt layout [d][j]

    const int bh = blockIdx.y;                    // b*NH + h
    const int qi = (gridDim.x - 1) - blockIdx.x;  // heavy q-tiles first
    const int q0 = qi * QT;
    const int tid  = threadIdx.x;
    const int warp = tid >> 5;
    const int lane = tid & 31;
    const int g  = lane >> 2;
    const int tg = lane & 3;
    const int r0 = warp * 16 + g;                 // local S/O row (also +8)

    const int aRow = warp * 16 + (lane & 7) + ((lane >> 3) & 1) * 8;
    const int aCol = (lane >> 4) * 4;
    const int bRow = (lane & 7) + (lane >> 4) * 8;
    const int bCol = ((lane >> 3) & 1) * 4;

    // P shuffle-transpose source lanes
    const int src1 = (lane & 28) | (tg >> 1);
    const int src2 = src1 + 2;
    const bool odd = (tg & 1);

    const float* __restrict__ qp = g_q + (size_t)bh * T_SEQ * HS;
    const float* __restrict__ kp = g_k + (size_t)bh * T_SEQ * HS;
    const float* __restrict__ vp = g_v + (size_t)bh * T_SEQ * HS;

    // Load Q tile (already tf32-rounded): plain copy, 128 rows x 64 d
#pragma unroll
    for (int i = 0; i < 8; i++) {
        const int f = tid + 256 * i;
        const int j = f >> 4;
        const int d4 = (f & 15) * 4;
        *(float4*)&Qs[j * FPAD + d4] =
            *(const float4*)(qp + (size_t)(q0 + j) * HS + d4);
    }

    auto issue_tile = [&](int kt) {
        const int k0 = kt * 64;
        float* K = Kb + (kt & 1) * TILE68;
        float* V = Vb + (kt & 1) * TILE68;
#pragma unroll
        for (int i = 0; i < 4; i++) {
            const int f = tid + 256 * i;
            const int j = f >> 4;
            const int d4 = (f & 15) * 4;
            cpa16(&K[j * FPAD + d4], kp + (size_t)(k0 + j) * HS + d4);
        }
        const int d  = tid & 63;
        const int j0 = (tid >> 6) * 16;
#pragma unroll
        for (int i = 0; i < 16; i++)
            cpa4(&V[d * FPAD + j0 + i],
                 vp + (size_t)(k0 + j0 + i) * HS + d);
        CP_COMMIT();
    };

    float m[2] = {-INFINITY, -INFINITY};
    float l[2] = {0.f, 0.f};
    float co[8][4];
#pragma unroll
    for (int ni = 0; ni < 8; ni++)
#pragma unroll
        for (int c = 0; c < 4; c++) co[ni][c] = 0.f;

    const int ntiles = 2 * qi + 2;
    issue_tile(0);

    for (int kt = 0; kt < ntiles; kt++) {
        const int k0 = kt * 64;
        const bool need_mask = (kt >= 2 * qi);
        const bool active = !(kt == 2 * qi + 1 && warp < 4);

        CP_WAIT0();          // tile kt arrived (only outstanding group)
        __syncthreads();     // visible to all; prev compute done
        if (kt + 1 < ntiles) issue_tile(kt + 1);   // prefetch other buffer

        if (active) {
            const float* Ks = Kb + (kt & 1) * TILE68;
            const float* Vt = Vb + (kt & 1) * TILE68;

            float cs[8][4];
#pragma unroll
            for (int ni = 0; ni < 8; ni++)
#pragma unroll
                for (int c = 0; c < 4; c++) cs[ni][c] = 0.f;

#pragma unroll
            for (int k8 = 0; k8 < HS; k8 += 8) {
                uint32_t a[4];
                ldsm4(a, &Qs[aRow * FPAD + aCol + k8]);
#pragma unroll
                for (int nn = 0; nn < 4; nn++) {
                    uint32_t b[4];
                    ldsm4(b, &Ks[(nn * 16 + bRow) * FPAD + bCol + k8]);
                    MMA_TF32(cs[2 * nn],     a[0], a[1], a[2], a[3], b[0], b[1]);
                    MMA_TF32(cs[2 * nn + 1], a[0], a[1], a[2], a[3], b[2], b[3]);
                }
            }

            float mt[2] = {-INFINITY, -INFINITY};
#pragma unroll
            for (int ni = 0; ni < 8; ni++) {
#pragma unroll
                for (int c = 0; c < 4; c++) {
                    float v = cs[ni][c] * 0.03125f;
                    if (need_mask) {
                        const int col = k0 + ni * 8 + 2 * tg + (c & 1);
                        const int row = q0 + r0 + 8 * (c >> 1);
                        if (col > row) v = -INFINITY;
                    }
                    cs[ni][c] = v;
                    mt[c >> 1] = fmaxf(mt[c >> 1], v);
                }
            }
#pragma unroll
            for (int h2 = 0; h2 < 2; h2++) {
                mt[h2] = fmaxf(mt[h2], __shfl_xor_sync(0xffffffffu, mt[h2], 1));
                mt[h2] = fmaxf(mt[h2], __shfl_xor_sync(0xffffffffu, mt[h2], 2));
            }
            float alpha[2];
#pragma unroll
            for (int h2 = 0; h2 < 2; h2++) {
                const float mnew = fmaxf(m[h2], mt[h2]);
                alpha[h2] = __expf(m[h2] - mnew);
                m[h2] = mnew;
            }
            float rs[2] = {0.f, 0.f};
#pragma unroll
            for (int ni = 0; ni < 8; ni++) {
#pragma unroll
                for (int c = 0; c < 4; c++) {
                    const float p = __expf(cs[ni][c] - m[c >> 1]);
                    cs[ni][c] = p;
                    rs[c >> 1] += p;
                }
            }
#pragma unroll
            for (int h2 = 0; h2 < 2; h2++) {
                rs[h2] += __shfl_xor_sync(0xffffffffu, rs[h2], 1);
                rs[h2] += __shfl_xor_sync(0xffffffffu, rs[h2], 2);
                l[h2] = l[h2] * alpha[h2] + rs[h2];
            }
#pragma unroll
            for (int ni = 0; ni < 8; ni++)
#pragma unroll
                for (int c = 0; c < 4; c++) co[ni][c] *= alpha[c >> 1];

            // ---- O += P V : P C-frag -> A-frag via warp shuffles ----
#pragma unroll
            for (int kk = 0; kk < 8; kk++) {
                const float x0 = __shfl_sync(0xffffffffu, cs[kk][0], src1);
                const float x1 = __shfl_sync(0xffffffffu, cs[kk][1], src1);
                const float x2 = __shfl_sync(0xffffffffu, cs[kk][2], src1);
                const float x3 = __shfl_sync(0xffffffffu, cs[kk][3], src1);
                const float y0 = __shfl_sync(0xffffffffu, cs[kk][0], src2);
                const float y1 = __shfl_sync(0xffffffffu, cs[kk][1], src2);
                const float y2 = __shfl_sync(0xffffffffu, cs[kk][2], src2);
                const float y3 = __shfl_sync(0xffffffffu, cs[kk][3], src2);
                const uint32_t a0 = f2tf32(odd ? x1 : x0);
                const uint32_t a1 = f2tf32(odd ? x3 : x2);
                const uint32_t a2 = f2tf32(odd ? y1 : y0);
                const uint32_t a3 = f2tf32(odd ? y3 : y2);
#pragma unroll
                for (int nn = 0; nn < 4; nn++) {
                    uint32_t b[4];
                    ldsm4(b, &Vt[(nn * 16 + bRow) * FPAD + bCol + 8 * kk]);
                    MMA_TF32(co[2 * nn],     a0, a1, a2, a3, b[0], b[1]);
                    MMA_TF32(co[2 * nn + 1], a0, a1, a2, a3, b[2], b[3]);
                }
            }
        }
    }

    // ---- epilogue: O /= l, write [B,T,C] ----
    const int b = bh >> 4;
    const int h = bh & 15;
    const float inv0 = 1.f / l[0];
    const float inv1 = 1.f / l[1];
    const size_t base0 = ((size_t)(b * T_SEQ + q0 + r0)) * CDIM + h * HS;
    const size_t base1 = ((size_t)(b * T_SEQ + q0 + r0 + 8)) * CDIM + h * HS;
#pragma unroll
    for (int ni = 0; ni < 8; ni++) {
        const int d = ni * 8 + 2 * tg;
        *(float2*)(out + base0 + d) = make_float2(co[ni][0] * inv0, co[ni][1] * inv0);
        *(float2*)(out + base1 + d) = make_float2(co[ni][2] * inv1, co[ni][3] * inv1);
    }
}

// ---------------------------------------------------------------------------
extern "C" void kernel_launch(void* const* d_in, const int* in_sizes, int n_in,
                              void* d_out, int out_size)
{
    const float* x  = (const float*)d_in[0];
    const float* Wq = (const float*)d_in[1];
    const float* Wk = (const float*)d_in[2];
    const float* Wv = (const float*)d_in[3];
    float* out = (float*)d_out;

    cvt_inputs<<<1024, 256>>>(x, Wq, Wk, Wv);

    const int gsmem = 2 * (GBM + GBN) * APITCH * (int)sizeof(float); // 73728
    cudaFuncSetAttribute(qkv_gemm_tf32,
                         cudaFuncAttributeMaxDynamicSharedMemorySize, gsmem);
    dim3 ggrid(CDIM / GBN, (BATCH * T_SEQ) / GBM, 3);
    qkv_gemm_tf32<<<ggrid, 256, gsmem>>>();

    const int fsmem = (QT + 4 * 64) * FPAD * (int)sizeof(float);     // 104448
    cudaFuncSetAttribute(flash_attn7,
                         cudaFuncAttributeMaxDynamicSharedMemorySize, fsmem);
    dim3 fgrid(T_SEQ / QT, BATCH * NH);
    flash_attn7<<<fgrid, 256, fsmem>>>(out);
}

// round 16
// speedup vs baseline: 1.0191x; 1.0191x over previous
#include <cuda_runtime.h>
#include <math.h>
#include <stdint.h>

// Problem constants
#define BATCH 2
#define T_SEQ 2048
#define CDIM  1024
#define NH    16
#define HS    64
#define QKV_ELEMS (BATCH * NH * T_SEQ * HS)   // 4 M floats = 16 MB each

// -2/1024 * ln(10000)
#define ROPE_COEF (-0.017988211f)

// Scratch (device globals — no allocation allowed in kernel_launch)
__device__ float g_q[QKV_ELEMS];
__device__ float g_k[QKV_ELEMS];
__device__ float g_v[QKV_ELEMS];
__device__ float g_x[BATCH * T_SEQ * CDIM];   // tf32-rounded x
__device__ float g_w[3 * CDIM * CDIM];        // tf32-rounded Wq|Wk|Wv

__device__ __forceinline__ uint32_t f2tf32(float f) {
    uint32_t r;
    asm("cvt.rna.tf32.f32 %0, %1;" : "=r"(r) : "f"(f));
    return r;
}
__device__ __forceinline__ float f2tf32f(float f) {
    return __uint_as_float(f2tf32(f));
}

#define MMA_TF32(C, A0, A1, A2, A3, B0, B1)                                    \
    asm volatile(                                                              \
        "mma.sync.aligned.m16n8k8.row.col.f32.tf32.tf32.f32 "                  \
        "{%0,%1,%2,%3}, {%4,%5,%6,%7}, {%8,%9}, {%0,%1,%2,%3};"                \
        : "+f"((C)[0]), "+f"((C)[1]), "+f"((C)[2]), "+f"((C)[3])               \
        : "r"(A0), "r"(A1), "r"(A2), "r"(A3), "r"(B0), "r"(B1))

// ldmatrix x4: four 8-row x 16B matrices; per-lane row addresses.
__device__ __forceinline__ void ldsm4(uint32_t* r, const float* p) {
    uint32_t addr = (uint32_t)__cvta_generic_to_shared(p);
    asm volatile(
        "ldmatrix.sync.aligned.m8n8.x4.shared.b16 {%0,%1,%2,%3}, [%4];"
        : "=r"(r[0]), "=r"(r[1]), "=r"(r[2]), "=r"(r[3]) : "r"(addr));
}

// cp.async helpers
__device__ __forceinline__ void cpa16(float* dst, const float* src) {
    uint32_t d = (uint32_t)__cvta_generic_to_shared(dst);
    asm volatile("cp.async.cg.shared.global [%0], [%1], 16;" :: "r"(d), "l"(src));
}
__device__ __forceinline__ void cpa4(float* dst, const float* src) {
    uint32_t d = (uint32_t)__cvta_generic_to_shared(dst);
    asm volatile("cp.async.ca.shared.global [%0], [%1], 4;" :: "r"(d), "l"(src));
}
#define CP_COMMIT() asm volatile("cp.async.commit_group;" ::: "memory")
#define CP_WAIT0()  asm volatile("cp.async.wait_group 0;" ::: "memory")
#define CP_WAIT1()  asm volatile("cp.async.wait_group 1;" ::: "memory")

// ---------------------------------------------------------------------------
// Kernel 0: pre-round x and W to RNA tf32 (hoists all input cvt out of GEMM).
// ---------------------------------------------------------------------------
#define NX4 (BATCH * T_SEQ * CDIM / 4)   // 1 M float4
#define NW4 (CDIM * CDIM / 4)            // 256 K float4 per matrix

__global__ __launch_bounds__(256) void cvt_inputs(
    const float* __restrict__ x,
    const float* __restrict__ Wq,
    const float* __restrict__ Wk,
    const float* __restrict__ Wv)
{
    const int total = NX4 + 3 * NW4;
    for (int idx = blockIdx.x * 256 + threadIdx.x; idx < total;
         idx += gridDim.x * 256) {
        const float4* src;
        float4* dst;
        if (idx < NX4) {
            src = (const float4*)x + idx;
            dst = (float4*)g_x + idx;
        } else {
            const int r = idx - NX4;
            const int w = r / NW4;
            const int o = r - w * NW4;
            const float* W = (w == 0) ? Wq : ((w == 1) ? Wk : Wv);
            src = (const float4*)W + o;
            dst = (float4*)g_w + (size_t)w * NW4 + o;
        }
        float4 v = *src;
        *dst = make_float4(f2tf32f(v.x), f2tf32f(v.y),
                           f2tf32f(v.z), f2tf32f(v.w));
    }
}

// ---------------------------------------------------------------------------
// Kernel A: out = x @ W^T via tf32 mma, cp.async 3-stage pipeline,
// fused RoPE epilogue, outputs tf32-rounded [B,H,T,HS].
// Block tile 128x128 (two heads), 8 warps of 32x64, BK=32.
// Grid: (8, 32, 3), Block: 256.  smem = 3*(128+128)*36*4 = 110592 B;
// __launch_bounds__(256,2) requests 2 blocks/SM (216 KB <= 228 KB carveout)
// to hide per-stage barrier + mma latency (16 warps/SM).
// ---------------------------------------------------------------------------
#define GBM 128
#define GBN 128
#define GBK 32
#define APITCH 36
#define GTILE (GBM * APITCH)   // floats per A (or B) stage buffer

__global__ __launch_bounds__(256, 2) void qkv_gemm_tf32()
{
    extern __shared__ float gsm[];
    float* As = gsm;                  // [3][GBM*APITCH]
    float* Bs = gsm + 3 * GTILE;      // [3][GBN*APITCH]

    const int z = blockIdx.z;
    const float* __restrict__ X = g_x;
    const float* __restrict__ W = g_w + (size_t)z * CDIM * CDIM;
    float* __restrict__ out = (z == 0) ? g_q : ((z == 1) ? g_k : g_v);

    const int m0 = blockIdx.y * GBM;
    const int n0 = blockIdx.x * GBN;

    const int tid  = threadIdx.x;
    const int warp = tid >> 5;
    const int lane = tid & 31;
    const int g    = lane >> 2;
    const int tg   = lane & 3;

    const int wm = warp >> 1;          // 0..3 (32-row tile)
    const int wn = warp & 1;           // 0..1 (64-col tile)

    // ldmatrix per-lane source rows/cols
    const int arow = wm * 32 + (lane & 7) + ((lane >> 3) & 1) * 8;
    const int acol = (lane >> 4) * 4;
    const int brow = wn * 64 + (lane & 7) + (lane >> 4) * 8;
    const int bcol = ((lane >> 3) & 1) * 4;

    // cp.async loader mapping: 1024 float4 per tile each for A and B
    const int lrow = tid >> 3;             // 0..31 base row (x4 iters -> 128)
    const int lc4  = (tid & 7) * 4;        // 0..28

    auto issue_tile = [&](int s) {
        float* A = As + (s % 3) * GTILE;
        float* B = Bs + (s % 3) * GTILE;
        const int kofs = s * GBK + lc4;
#pragma unroll
        for (int i = 0; i < 4; i++) {
            const int r = lrow + 32 * i;
            cpa16(&A[r * APITCH + lc4], X + (size_t)(m0 + r) * CDIM + kofs);
            cpa16(&B[r * APITCH + lc4], W + (size_t)(n0 + r) * CDIM + kofs);
        }
    };

    float c[2][8][4];
#pragma unroll
    for (int mi = 0; mi < 2; mi++)
#pragma unroll
        for (int ni = 0; ni < 8; ni++)
#pragma unroll
            for (int r = 0; r < 4; r++) c[mi][ni][r] = 0.f;

    auto compute_stage = [&](int s) {
        const float* A = As + (s % 3) * GTILE;
        const float* B = Bs + (s % 3) * GTILE;
#pragma unroll
        for (int k8 = 0; k8 < GBK; k8 += 8) {
            uint32_t a[2][4], b[4][4];
            ldsm4(a[0], &A[arow * APITCH + acol + k8]);
            ldsm4(a[1], &A[(arow + 16) * APITCH + acol + k8]);
#pragma unroll
            for (int nn = 0; nn < 4; nn++)
                ldsm4(b[nn], &B[(brow + nn * 16) * APITCH + bcol + k8]);
            // data pre-rounded to tf32 by cvt_inputs — no cvt here
#pragma unroll
            for (int mi = 0; mi < 2; mi++)
#pragma unroll
                for (int nn = 0; nn < 4; nn++) {
                    MMA_TF32(c[mi][2 * nn],     a[mi][0], a[mi][1], a[mi][2],
                             a[mi][3], b[nn][0], b[nn][1]);
                    MMA_TF32(c[mi][2 * nn + 1], a[mi][0], a[mi][1], a[mi][2],
                             a[mi][3], b[nn][2], b[nn][3]);
                }
        }
    };

    const int stages = CDIM / GBK;   // 32

    issue_tile(0); CP_COMMIT();
    issue_tile(1); CP_COMMIT();
    CP_WAIT1();                      // stage 0 arrived
    __syncthreads();

    for (int s = 0; s < stages; s++) {
        compute_stage(s);
        if (s + 2 < stages) issue_tile(s + 2);
        CP_COMMIT();                 // empty group at tail keeps FIFO count
        CP_WAIT1();                  // stage s+1 arrived (in-order retire)
        __syncthreads();             // buffer (s+2)%3 free for next issue
    }

    // ---- epilogue: RoPE (z<2) + tf32-round + store [B,H,T,HS] ----
#pragma unroll
    for (int mi = 0; mi < 2; mi++) {
#pragma unroll
        for (int ni = 0; ni < 8; ni++) {
            const int dg = wn * 64 + ni * 8 + 2 * tg;    // 0..127
            const int h  = blockIdx.x * 2 + (dg >> 6);
            const int d  = dg & 63;
            float theta = 0.f;
            if (z < 2) theta = expf((float)(d >> 1) * ROPE_COEF);
#pragma unroll
            for (int half = 0; half < 2; half++) {
                const int m = m0 + wm * 32 + mi * 16 + g + half * 8;
                const int t = m & (T_SEQ - 1);
                const int b = m >> 11;
                const float v0 = c[mi][ni][half * 2 + 0];
                const float v1 = c[mi][ni][half * 2 + 1];
                const size_t base =
                    (((size_t)(b * NH + h) * T_SEQ) + t) * HS + d;
                if (z < 2) {
                    // fp32 Cody-Waite mod 2pi (fast-math-proof)
                    const float ang = (float)t * theta;
                    const float nq = floorf(ang * 0.15915494309f);
                    float r = fmaf(-nq, 6.28125f, ang);
                    r = fmaf(-nq, 1.9353072e-3f, r);
                    const float sn = __sinf(r);
                    const float cs = __cosf(r);
                    *(float2*)(out + base) =
                        make_float2(f2tf32f(v0 * cs - v1 * sn),
                                    f2tf32f(v1 * cs + v0 * sn));
                } else {
                    *(float2*)(out + base) =
                        make_float2(f2tf32f(v0), f2tf32f(v1));
                }
            }
        }
    }
}

// ---------------------------------------------------------------------------
// Kernel B: tf32 mma flash attention, cp.async double-buffered K/V (inputs
// pre-rounded to tf32), register-shuffle P transpose. One barrier per tile.
// (unchanged from R13)
// ---------------------------------------------------------------------------
#define FPAD 68
#define QT 128
#define TILE68 (64 * FPAD)

__global__ __launch_bounds__(256, 2) void flash_attn7(float* __restrict__ out)
{
    extern __shared__ float sm[];
    float* Qs = sm;                       // [128][68]  Qs[q][d]   (tf32)
    float* Kb = Qs + QT * FPAD;           // [2][64][68] keys row-major
    float* Vb = Kb + 2 * TILE68;          // [2][64][68] Vt layout [d][j]

    const int bh = blockIdx.y;                    // b*NH + h
    const int qi = (gridDim.x - 1) - blockIdx.x;  // heavy q-tiles first
    const int q0 = qi * QT;
    const int tid  = threadIdx.x;
    const int warp = tid >> 5;
    const int lane = tid & 31;
    const int g  = lane >> 2;
    const int tg = lane & 3;
    const int r0 = warp * 16 + g;                 // local S/O row (also +8)

    const int aRow = warp * 16 + (lane & 7) + ((lane >> 3) & 1) * 8;
    const int aCol = (lane >> 4) * 4;
    const int bRow = (lane & 7) + (lane >> 4) * 8;
    const int bCol = ((lane >> 3) & 1) * 4;

    // P shuffle-transpose source lanes
    const int src1 = (lane & 28) | (tg >> 1);
    const int src2 = src1 + 2;
    const bool odd = (tg & 1);

    const float* __restrict__ qp = g_q + (size_t)bh * T_SEQ * HS;
    const float* __restrict__ kp = g_k + (size_t)bh * T_SEQ * HS;
    const float* __restrict__ vp = g_v + (size_t)bh * T_SEQ * HS;

    // Load Q tile (already tf32-rounded): plain copy, 128 rows x 64 d
#pragma unroll
    for (int i = 0; i < 8; i++) {
        const int f = tid + 256 * i;
        const int j = f >> 4;
        const int d4 = (f & 15) * 4;
        *(float4*)&Qs[j * FPAD + d4] =
            *(const float4*)(qp + (size_t)(q0 + j) * HS + d4);
    }

    auto issue_tile = [&](int kt) {
        const int k0 = kt * 64;
        float* K = Kb + (kt & 1) * TILE68;
        float* V = Vb + (kt & 1) * TILE68;
#pragma unroll
        for (int i = 0; i < 4; i++) {
            const int f = tid + 256 * i;
            const int j = f >> 4;
            const int d4 = (f & 15) * 4;
            cpa16(&K[j * FPAD + d4], kp + (size_t)(k0 + j) * HS + d4);
        }
        const int d  = tid & 63;
        const int j0 = (tid >> 6) * 16;
#pragma unroll
        for (int i = 0; i < 16; i++)
            cpa4(&V[d * FPAD + j0 + i],
                 vp + (size_t)(k0 + j0 + i) * HS + d);
        CP_COMMIT();
    };

    float m[2] = {-INFINITY, -INFINITY};
    float l[2] = {0.f, 0.f};
    float co[8][4];
#pragma unroll
    for (int ni = 0; ni < 8; ni++)
#pragma unroll
        for (int c = 0; c < 4; c++) co[ni][c] = 0.f;

    const int ntiles = 2 * qi + 2;
    issue_tile(0);

    for (int kt = 0; kt < ntiles; kt++) {
        const int k0 = kt * 64;
        const bool need_mask = (kt >= 2 * qi);
        const bool active = !(kt == 2 * qi + 1 && warp < 4);

        CP_WAIT0();          // tile kt arrived (only outstanding group)
        __syncthreads();     // visible to all; prev compute done
        if (kt + 1 < ntiles) issue_tile(kt + 1);   // prefetch other buffer

        if (active) {
            const float* Ks = Kb + (kt & 1) * TILE68;
            const float* Vt = Vb + (kt & 1) * TILE68;

            float cs[8][4];
#pragma unroll
            for (int ni = 0; ni < 8; ni++)
#pragma unroll
                for (int c = 0; c < 4; c++) cs[ni][c] = 0.f;

#pragma unroll
            for (int k8 = 0; k8 < HS; k8 += 8) {
                uint32_t a[4];
                ldsm4(a, &Qs[aRow * FPAD + aCol + k8]);
#pragma unroll
                for (int nn = 0; nn < 4; nn++) {
                    uint32_t b[4];
                    ldsm4(b, &Ks[(nn * 16 + bRow) * FPAD + bCol + k8]);
                    MMA_TF32(cs[2 * nn],     a[0], a[1], a[2], a[3], b[0], b[1]);
                    MMA_TF32(cs[2 * nn + 1], a[0], a[1], a[2], a[3], b[2], b[3]);
                }
            }

            float mt[2] = {-INFINITY, -INFINITY};
#pragma unroll
            for (int ni = 0; ni < 8; ni++) {
#pragma unroll
                for (int c = 0; c < 4; c++) {
                    float v = cs[ni][c] * 0.03125f;
                    if (need_mask) {
                        const int col = k0 + ni * 8 + 2 * tg + (c & 1);
                        const int row = q0 + r0 + 8 * (c >> 1);
                        if (col > row) v = -INFINITY;
                    }
                    cs[ni][c] = v;
                    mt[c >> 1] = fmaxf(mt[c >> 1], v);
                }
            }
#pragma unroll
            for (int h2 = 0; h2 < 2; h2++) {
                mt[h2] = fmaxf(mt[h2], __shfl_xor_sync(0xffffffffu, mt[h2], 1));
                mt[h2] = fmaxf(mt[h2], __shfl_xor_sync(0xffffffffu, mt[h2], 2));
            }
            float alpha[2];
#pragma unroll
            for (int h2 = 0; h2 < 2; h2++) {
                const float mnew = fmaxf(m[h2], mt[h2]);
                alpha[h2] = __expf(m[h2] - mnew);
                m[h2] = mnew;
            }
            float rs[2] = {0.f, 0.f};
#pragma unroll
            for (int ni = 0; ni < 8; ni++) {
#pragma unroll
                for (int c = 0; c < 4; c++) {
                    const float p = __expf(cs[ni][c] - m[c >> 1]);
                    cs[ni][c] = p;
                    rs[c >> 1] += p;
                }
            }
#pragma unroll
            for (int h2 = 0; h2 < 2; h2++) {
                rs[h2] += __shfl_xor_sync(0xffffffffu, rs[h2], 1);
                rs[h2] += __shfl_xor_sync(0xffffffffu, rs[h2], 2);
                l[h2] = l[h2] * alpha[h2] + rs[h2];
            }
#pragma unroll
            for (int ni = 0; ni < 8; ni++)
#pragma unroll
                for (int c = 0; c < 4; c++) co[ni][c] *= alpha[c >> 1];

            // ---- O += P V : P C-frag -> A-frag via warp shuffles ----
#pragma unroll
            for (int kk = 0; kk < 8; kk++) {
                const float x0 = __shfl_sync(0xffffffffu, cs[kk][0], src1);
                const float x1 = __shfl_sync(0xffffffffu, cs[kk][1], src1);
                const float x2 = __shfl_sync(0xffffffffu, cs[kk][2], src1);
                const float x3 = __shfl_sync(0xffffffffu, cs[kk][3], src1);
                const float y0 = __shfl_sync(0xffffffffu, cs[kk][0], src2);
                const float y1 = __shfl_sync(0xffffffffu, cs[kk][1], src2);
                const float y2 = __shfl_sync(0xffffffffu, cs[kk][2], src2);
                const float y3 = __shfl_sync(0xffffffffu, cs[kk][3], src2);
                const uint32_t a0 = f2tf32(odd ? x1 : x0);
                const uint32_t a1 = f2tf32(odd ? x3 : x2);
                const uint32_t a2 = f2tf32(odd ? y1 : y0);
                const uint32_t a3 = f2tf32(odd ? y3 : y2);
#pragma unroll
                for (int nn = 0; nn < 4; nn++) {
                    uint32_t b[4];
                    ldsm4(b, &Vt[(nn * 16 + bRow) * FPAD + bCol + 8 * kk]);
                    MMA_TF32(co[2 * nn],     a0, a1, a2, a3, b[0], b[1]);
                    MMA_TF32(co[2 * nn + 1], a0, a1, a2, a3, b[2], b[3]);
                }
            }
        }
    }

    // ---- epilogue: O /= l, write [B,T,C] ----
    const int b = bh >> 4;
    const int h = bh & 15;
    const float inv0 = 1.f / l[0];
    const float inv1 = 1.f / l[1];
    const size_t base0 = ((size_t)(b * T_SEQ + q0 + r0)) * CDIM + h * HS;
    const size_t base1 = ((size_t)(b * T_SEQ + q0 + r0 + 8)) * CDIM + h * HS;
#pragma unroll
    for (int ni = 0; ni < 8; ni++) {
        const int d = ni * 8 + 2 * tg;
        *(float2*)(out + base0 + d) = make_float2(co[ni][0] * inv0, co[ni][1] * inv0);
        *(float2*)(out + base1 + d) = make_float2(co[ni][2] * inv1, co[ni][3] * inv1);
    }
}

// ---------------------------------------------------------------------------
extern "C" void kernel_launch(void* const* d_in, const int* in_sizes, int n_in,
                              void* d_out, int out_size)
{
    const float* x  = (const float*)d_in[0];
    const float* Wq = (const float*)d_in[1];
    const float* Wk = (const float*)d_in[2];
    const float* Wv = (const float*)d_in[3];
    float* out = (float*)d_out;

    cvt_inputs<<<1024, 256>>>(x, Wq, Wk, Wv);

    const int gsmem = 3 * (GBM + GBN) * APITCH * (int)sizeof(float); // 110592
    cudaFuncSetAttribute(qkv_gemm_tf32,
                         cudaFuncAttributeMaxDynamicSharedMemorySize, gsmem);
    dim3 ggrid(CDIM / GBN, (BATCH * T_SEQ) / GBM, 3);
    qkv_gemm_tf32<<<ggrid, 256, gsmem>>>();

    const int fsmem = (QT + 4 * 64) * FPAD * (int)sizeof(float);     // 104448
    cudaFuncSetAttribute(flash_attn7,
                         cudaFuncAttributeMaxDynamicSharedMemorySize, fsmem);
    dim3 fgrid(T_SEQ / QT, BATCH * NH);
    flash_attn7<<<fgrid, 256, fsmem>>>(out);
}

// round 17
// speedup vs baseline: 1.7994x; 1.7657x over previous
#include <cuda_runtime.h>
#include <cuda_fp16.h>
#include <math.h>
#include <stdint.h>

// Problem constants
#define BATCH 2
#define T_SEQ 2048
#define CDIM  1024
#define NH    16
#define HS    64
#define QKV_ELEMS (BATCH * NH * T_SEQ * HS)   // 4 M elems

// -2/1024 * ln(10000)
#define ROPE_COEF (-0.017988211f)

// Scratch (device globals — no allocation allowed in kernel_launch)
__device__ __half g_q[QKV_ELEMS];
__device__ __half g_k[QKV_ELEMS];
__device__ __half g_v[QKV_ELEMS];
__device__ __half g_x[BATCH * T_SEQ * CDIM];   // fp16 x
__device__ __half g_w[3 * CDIM * CDIM];        // fp16 Wq|Wk|Wv

// pack two fp32 -> f16x2 (lo in low half)
__device__ __forceinline__ uint32_t packh(float lo, float hi) {
    uint32_t r;
    asm("cvt.rn.f16x2.f32 %0, %1, %2;" : "=r"(r) : "f"(hi), "f"(lo));
    return r;
}

#define MMA_F16(C, A0, A1, A2, A3, B0, B1)                                     \
    asm volatile(                                                              \
        "mma.sync.aligned.m16n8k16.row.col.f32.f16.f16.f32 "                   \
        "{%0,%1,%2,%3}, {%4,%5,%6,%7}, {%8,%9}, {%0,%1,%2,%3};"                \
        : "+f"((C)[0]), "+f"((C)[1]), "+f"((C)[2]), "+f"((C)[3])               \
        : "r"(A0), "r"(A1), "r"(A2), "r"(A3), "r"(B0), "r"(B1))

// ldmatrix x4 (b16 rows of 16B); per-lane row addresses.
__device__ __forceinline__ void ldsm4(uint32_t* r, const void* p) {
    uint32_t addr = (uint32_t)__cvta_generic_to_shared(p);
    asm volatile(
        "ldmatrix.sync.aligned.m8n8.x4.shared.b16 {%0,%1,%2,%3}, [%4];"
        : "=r"(r[0]), "=r"(r[1]), "=r"(r[2]), "=r"(r[3]) : "r"(addr));
}
__device__ __forceinline__ void ldsm4t(uint32_t* r, const void* p) {
    uint32_t addr = (uint32_t)__cvta_generic_to_shared(p);
    asm volatile(
        "ldmatrix.sync.aligned.m8n8.x4.trans.shared.b16 {%0,%1,%2,%3}, [%4];"
        : "=r"(r[0]), "=r"(r[1]), "=r"(r[2]), "=r"(r[3]) : "r"(addr));
}

// cp.async helpers (16 B)
__device__ __forceinline__ void cpa16h(__half* dst, const __half* src) {
    uint32_t d = (uint32_t)__cvta_generic_to_shared(dst);
    asm volatile("cp.async.cg.shared.global [%0], [%1], 16;" :: "r"(d), "l"(src));
}
#define CP_COMMIT() asm volatile("cp.async.commit_group;" ::: "memory")
#define CP_WAIT0()  asm volatile("cp.async.wait_group 0;" ::: "memory")
#define CP_WAIT1()  asm volatile("cp.async.wait_group 1;" ::: "memory")

// ---------------------------------------------------------------------------
// Kernel 0: convert x and W to fp16 (RN) — hoists all input rounding.
// ---------------------------------------------------------------------------
#define NX4 (BATCH * T_SEQ * CDIM / 4)   // 1 M float4
#define NW4 (CDIM * CDIM / 4)            // 256 K float4 per matrix

__global__ __launch_bounds__(256) void cvt_inputs(
    const float* __restrict__ x,
    const float* __restrict__ Wq,
    const float* __restrict__ Wk,
    const float* __restrict__ Wv)
{
    const int total = NX4 + 3 * NW4;
    for (int idx = blockIdx.x * 256 + threadIdx.x; idx < total;
         idx += gridDim.x * 256) {
        const float4* src;
        __half* dst;
        if (idx < NX4) {
            src = (const float4*)x + idx;
            dst = g_x + (size_t)idx * 4;
        } else {
            const int r = idx - NX4;
            const int w = r / NW4;
            const int o = r - w * NW4;
            const float* W = (w == 0) ? Wq : ((w == 1) ? Wk : Wv);
            src = (const float4*)W + o;
            dst = g_w + (size_t)w * (CDIM * CDIM) + (size_t)o * 4;
        }
        float4 v = *src;
        uint2 u = make_uint2(packh(v.x, v.y), packh(v.z, v.w));
        *(uint2*)dst = u;
    }
}

// ---------------------------------------------------------------------------
// Kernel A: out = x @ W^T via fp16 mma (m16n8k16), cp.async 3-stage pipeline,
// fused RoPE epilogue, outputs fp16 [B,H,T,HS].
// Block tile 128x128 (two heads), 8 warps of 32x64, BK=32.
// Grid: (8, 32, 3), Block: 256.  smem = 3*(128+128)*40*2 = 61440 B.
// ---------------------------------------------------------------------------
#define GBM 128
#define GBN 128
#define GBK 32
#define HPITCH 40                      // halves per row (32 + 8 pad)
#define GTILEH (GBM * HPITCH)          // halves per A (or B) stage buffer

__global__ __launch_bounds__(256, 2) void qkv_gemm_f16()
{
    extern __shared__ __half gsm[];
    __half* As = gsm;                  // [3][GBM*HPITCH]
    __half* Bs = gsm + 3 * GTILEH;     // [3][GBN*HPITCH]

    const int z = blockIdx.z;
    const __half* __restrict__ X = g_x;
    const __half* __restrict__ W = g_w + (size_t)z * CDIM * CDIM;
    __half* __restrict__ out = (z == 0) ? g_q : ((z == 1) ? g_k : g_v);

    const int m0 = blockIdx.y * GBM;
    const int n0 = blockIdx.x * GBN;

    const int tid  = threadIdx.x;
    const int warp = tid >> 5;
    const int lane = tid & 31;
    const int g    = lane >> 2;
    const int tg   = lane & 3;

    const int wm = warp >> 1;          // 0..3 (32-row tile)
    const int wn = warp & 1;           // 0..1 (64-col tile)

    // ldmatrix per-lane rows / half-offsets (k16 fragment layout)
    const int arow = wm * 32 + (lane & 7) + ((lane >> 3) & 1) * 8;
    const int aOff = (lane >> 4) * 8;
    const int brow0 = wn * 64 + (lane & 7) + ((lane >> 4) & 1) * 8;
    const int bOff = ((lane >> 3) & 1) * 8;

    // cp.async loader: 128 rows x 32 halves each for A and B; 2 cpa16/thread ea.
    const int lrow = tid >> 1;             // 0..127
    const int lka  = (tid & 1) * 16;       // 0 or 16 (halves)

    auto issue_tile = [&](int s) {
        __half* A = As + (s % 3) * GTILEH;
        __half* B = Bs + (s % 3) * GTILEH;
        const int kofs = s * GBK + lka;
        cpa16h(&A[lrow * HPITCH + lka],     X + (size_t)(m0 + lrow) * CDIM + kofs);
        cpa16h(&A[lrow * HPITCH + lka + 8], X + (size_t)(m0 + lrow) * CDIM + kofs + 8);
        cpa16h(&B[lrow * HPITCH + lka],     W + (size_t)(n0 + lrow) * CDIM + kofs);
        cpa16h(&B[lrow * HPITCH + lka + 8], W + (size_t)(n0 + lrow) * CDIM + kofs + 8);
    };

    float c[2][8][4];
#pragma unroll
    for (int mi = 0; mi < 2; mi++)
#pragma unroll
        for (int ni = 0; ni < 8; ni++)
#pragma unroll
            for (int r = 0; r < 4; r++) c[mi][ni][r] = 0.f;

    auto compute_stage = [&](int s) {
        const __half* A = As + (s % 3) * GTILEH;
        const __half* B = Bs + (s % 3) * GTILEH;
#pragma unroll
        for (int kg = 0; kg < 2; kg++) {             // two k16 groups
            uint32_t a[2][4], b[4][4];
            ldsm4(a[0], &A[arow * HPITCH + kg * 16 + aOff]);
            ldsm4(a[1], &A[(arow + 16) * HPITCH + kg * 16 + aOff]);
#pragma unroll
            for (int nn = 0; nn < 4; nn++)
                ldsm4(b[nn], &B[(brow0 + nn * 16) * HPITCH + kg * 16 + bOff]);
#pragma unroll
            for (int mi = 0; mi < 2; mi++)
#pragma unroll
                for (int nn = 0; nn < 4; nn++) {
                    MMA_F16(c[mi][2 * nn],     a[mi][0], a[mi][1], a[mi][2],
                            a[mi][3], b[nn][0], b[nn][1]);
                    MMA_F16(c[mi][2 * nn + 1], a[mi][0], a[mi][1], a[mi][2],
                            a[mi][3], b[nn][2], b[nn][3]);
                }
        }
    };

    const int stages = CDIM / GBK;   // 32

    issue_tile(0); CP_COMMIT();
    issue_tile(1); CP_COMMIT();
    CP_WAIT1();                      // stage 0 arrived
    __syncthreads();

    for (int s = 0; s < stages; s++) {
        compute_stage(s);
        if (s + 2 < stages) issue_tile(s + 2);
        CP_COMMIT();                 // empty group at tail keeps FIFO count
        CP_WAIT1();                  // stage s+1 arrived (in-order retire)
        __syncthreads();             // buffer (s+2)%3 free for next issue
    }

    // ---- epilogue: RoPE (z<2) + fp16 store [B,H,T,HS] ----
#pragma unroll
    for (int mi = 0; mi < 2; mi++) {
#pragma unroll
        for (int ni = 0; ni < 8; ni++) {
            const int dg = wn * 64 + ni * 8 + 2 * tg;    // 0..127
            const int h  = blockIdx.x * 2 + (dg >> 6);
            const int d  = dg & 63;
            float theta = 0.f;
            if (z < 2) theta = expf((float)(d >> 1) * ROPE_COEF);
#pragma unroll
            for (int half = 0; half < 2; half++) {
                const int m = m0 + wm * 32 + mi * 16 + g + half * 8;
                const int t = m & (T_SEQ - 1);
                const int b = m >> 11;
                const float v0 = c[mi][ni][half * 2 + 0];
                const float v1 = c[mi][ni][half * 2 + 1];
                const size_t base =
                    (((size_t)(b * NH + h) * T_SEQ) + t) * HS + d;
                if (z < 2) {
                    // fp32 Cody-Waite mod 2pi (fast-math-proof)
                    const float ang = (float)t * theta;
                    const float nq = floorf(ang * 0.15915494309f);
                    float r = fmaf(-nq, 6.28125f, ang);
                    r = fmaf(-nq, 1.9353072e-3f, r);
                    const float sn = __sinf(r);
                    const float cs = __cosf(r);
                    *(uint32_t*)(out + base) =
                        packh(v0 * cs - v1 * sn, v1 * cs + v0 * sn);
                } else {
                    *(uint32_t*)(out + base) = packh(v0, v1);
                }
            }
        }
    }
}

// ---------------------------------------------------------------------------
// Kernel B: fp16 mma (m16n8k16) flash attention, cp.async double-buffered K/V,
// P direct from C-frags (cvt.rn.f16x2), V B-frags via ldsm.trans.
// Block = 128 queries x 64-key tiles; 256 threads, 8 warps; warp owns 16 rows.
// smem: Q[128][72] + K[2][64][72] + V[2][64][72] fp16 = 55296 B.
// ---------------------------------------------------------------------------
#define BPITCH 72
#define QT 128
#define TILEH (64 * BPITCH)

__global__ __launch_bounds__(256, 2) void flash_attn8(float* __restrict__ out)
{
    extern __shared__ __half bsm[];
    __half* Qs = bsm;                 // [128][BPITCH]
    __half* Kb = Qs + QT * BPITCH;    // [2][64][BPITCH] keys row-major
    __half* Vb = Kb + 2 * TILEH;      // [2][64][BPITCH] V row-major

    const int bh = blockIdx.y;                    // b*NH + h
    const int qi = (gridDim.x - 1) - blockIdx.x;  // heavy q-tiles first
    const int q0 = qi * QT;
    const int tid  = threadIdx.x;
    const int warp = tid >> 5;
    const int lane = tid & 31;
    const int g  = lane >> 2;
    const int tg = lane & 3;
    const int r0 = warp * 16 + g;                 // local S/O row (also +8)

    // ldmatrix per-lane rows/offsets (proven in R10)
    const int aRow = warp * 16 + (lane & 7) + ((lane >> 3) & 1) * 8;
    const int aOff = (lane >> 4) * 8;                    // halves within k16
    const int kRow = (lane & 7) + ((lane >> 4) & 1) * 8; // key row (S B-frag)
    const int kOff = ((lane >> 3) & 1) * 8;
    const int vRow = (lane & 7) + ((lane >> 3) & 1) * 8; // key row (PV B-frag)
    const int vOff = (lane >> 4) * 8;

    const __half* __restrict__ qp = g_q + (size_t)bh * T_SEQ * HS;
    const __half* __restrict__ kp = g_k + (size_t)bh * T_SEQ * HS;
    const __half* __restrict__ vp = g_v + (size_t)bh * T_SEQ * HS;

    // Load Q tile (fp16, plain copy): 128 rows x 64 halves
#pragma unroll
    for (int i = 0; i < 4; i++) {
        const int f = tid + 256 * i;
        const int j = f >> 3;
        const int d8 = (f & 7) * 8;
        *(uint4*)&Qs[j * BPITCH + d8] =
            *(const uint4*)(qp + (size_t)(q0 + j) * HS + d8);
    }

    auto issue_tile = [&](int kt) {
        const int k0 = kt * 64;
        __half* K = Kb + (kt & 1) * TILEH;
        __half* V = Vb + (kt & 1) * TILEH;
#pragma unroll
        for (int i = 0; i < 2; i++) {
            const int f = tid + 256 * i;
            const int j = f >> 3;
            const int d8 = (f & 7) * 8;
            cpa16h(&K[j * BPITCH + d8], kp + (size_t)(k0 + j) * HS + d8);
            cpa16h(&V[j * BPITCH + d8], vp + (size_t)(k0 + j) * HS + d8);
        }
        CP_COMMIT();
    };

    float m[2] = {-INFINITY, -INFINITY};
    float l[2] = {0.f, 0.f};
    float co[8][4];
#pragma unroll
    for (int ni = 0; ni < 8; ni++)
#pragma unroll
        for (int c = 0; c < 4; c++) co[ni][c] = 0.f;

    const int ntiles = 2 * qi + 2;   // 64-key tiles covering [0, q0+128)
    issue_tile(0);

    for (int kt = 0; kt < ntiles; kt++) {
        const int k0 = kt * 64;
        const bool need_mask = (kt >= 2 * qi);
        // warps 0-3 (rows q0..q0+63) are fully masked on the last tile
        const bool active = !(kt == 2 * qi + 1 && warp < 4);

        CP_WAIT0();          // tile kt arrived (only outstanding group)
        __syncthreads();     // visible to all; prev compute done
        if (kt + 1 < ntiles) issue_tile(kt + 1);   // prefetch other buffer

        if (active) {
            const __half* Ks = Kb + (kt & 1) * TILEH;
            const __half* Vs = Vb + (kt & 1) * TILEH;

            // ---- S = Q K^T : warp rows [warp*16,+16) x 64 keys ----
            float cs[8][4];
#pragma unroll
            for (int ni = 0; ni < 8; ni++)
#pragma unroll
                for (int c = 0; c < 4; c++) cs[ni][c] = 0.f;

#pragma unroll
            for (int kg = 0; kg < 4; kg++) {          // k16 groups over d
                uint32_t a[4];
                ldsm4(a, &Qs[aRow * BPITCH + kg * 16 + aOff]);
#pragma unroll
                for (int nn = 0; nn < 4; nn++) {      // pairs of key-groups
                    uint32_t b[4];
                    ldsm4(b, &Ks[(nn * 16 + kRow) * BPITCH + kg * 16 + kOff]);
                    MMA_F16(cs[2 * nn],     a[0], a[1], a[2], a[3], b[0], b[1]);
                    MMA_F16(cs[2 * nn + 1], a[0], a[1], a[2], a[3], b[2], b[3]);
                }
            }

            // ---- scale + causal mask + online softmax ----
            float mt[2] = {-INFINITY, -INFINITY};
#pragma unroll
            for (int ni = 0; ni < 8; ni++) {
#pragma unroll
                for (int c = 0; c < 4; c++) {
                    float v = cs[ni][c] * 0.03125f;
                    if (need_mask) {
                        const int col = k0 + ni * 8 + 2 * tg + (c & 1);
                        const int row = q0 + r0 + 8 * (c >> 1);
                        if (col > row) v = -INFINITY;
                    }
                    cs[ni][c] = v;
                    mt[c >> 1] = fmaxf(mt[c >> 1], v);
                }
            }
#pragma unroll
            for (int h2 = 0; h2 < 2; h2++) {
                mt[h2] = fmaxf(mt[h2], __shfl_xor_sync(0xffffffffu, mt[h2], 1));
                mt[h2] = fmaxf(mt[h2], __shfl_xor_sync(0xffffffffu, mt[h2], 2));
            }
            float alpha[2];
#pragma unroll
            for (int h2 = 0; h2 < 2; h2++) {
                const float mnew = fmaxf(m[h2], mt[h2]);
                alpha[h2] = __expf(m[h2] - mnew);
                m[h2] = mnew;
            }
            float rs[2] = {0.f, 0.f};
#pragma unroll
            for (int ni = 0; ni < 8; ni++) {
#pragma unroll
                for (int c = 0; c < 4; c++) {
                    const float p = __expf(cs[ni][c] - m[c >> 1]);
                    cs[ni][c] = p;
                    rs[c >> 1] += p;
                }
            }
#pragma unroll
            for (int h2 = 0; h2 < 2; h2++) {
                rs[h2] += __shfl_xor_sync(0xffffffffu, rs[h2], 1);
                rs[h2] += __shfl_xor_sync(0xffffffffu, rs[h2], 2);
                l[h2] = l[h2] * alpha[h2] + rs[h2];
            }
#pragma unroll
            for (int ni = 0; ni < 8; ni++)
#pragma unroll
                for (int c = 0; c < 4; c++) co[ni][c] *= alpha[c >> 1];

            // ---- O += P V : P packed straight from C-frags ----
#pragma unroll
            for (int kg = 0; kg < 4; kg++) {          // 16-key groups
                const uint32_t a0 = packh(cs[2 * kg][0],     cs[2 * kg][1]);
                const uint32_t a1 = packh(cs[2 * kg][2],     cs[2 * kg][3]);
                const uint32_t a2 = packh(cs[2 * kg + 1][0], cs[2 * kg + 1][1]);
                const uint32_t a3 = packh(cs[2 * kg + 1][2], cs[2 * kg + 1][3]);
#pragma unroll
                for (int ng = 0; ng < 4; ng++) {      // pairs of 8-d groups
                    uint32_t b[4];
                    ldsm4t(b, &Vs[(kg * 16 + vRow) * BPITCH + ng * 16 + vOff]);
                    MMA_F16(co[2 * ng],     a0, a1, a2, a3, b[0], b[1]);
                    MMA_F16(co[2 * ng + 1], a0, a1, a2, a3, b[2], b[3]);
                }
            }
        }
    }

    // ---- epilogue: O /= l, write [B,T,C] (fp32) ----
    const int b = bh >> 4;
    const int h = bh & 15;
    const float inv0 = 1.f / l[0];
    const float inv1 = 1.f / l[1];
    const size_t base0 = ((size_t)(b * T_SEQ + q0 + r0)) * CDIM + h * HS;
    const size_t base1 = ((size_t)(b * T_SEQ + q0 + r0 + 8)) * CDIM + h * HS;
#pragma unroll
    for (int ni = 0; ni < 8; ni++) {
        const int d = ni * 8 + 2 * tg;
        *(float2*)(out + base0 + d) = make_float2(co[ni][0] * inv0, co[ni][1] * inv0);
        *(float2*)(out + base1 + d) = make_float2(co[ni][2] * inv1, co[ni][3] * inv1);
    }
}

// ---------------------------------------------------------------------------
extern "C" void kernel_launch(void* const* d_in, const int* in_sizes, int n_in,
                              void* d_out, int out_size)
{
    const float* x  = (const float*)d_in[0];
    const float* Wq = (const float*)d_in[1];
    const float* Wk = (const float*)d_in[2];
    const float* Wv = (const float*)d_in[3];
    float* out = (float*)d_out;

    cvt_inputs<<<1024, 256>>>(x, Wq, Wk, Wv);

    const int gsmem = 3 * (GBM + GBN) * HPITCH * 2;   // 61440 B
    cudaFuncSetAttribute(qkv_gemm_f16,
                         cudaFuncAttributeMaxDynamicSharedMemorySize, gsmem);
    dim3 ggrid(CDIM / GBN, (BATCH * T_SEQ) / GBM, 3);
    qkv_gemm_f16<<<ggrid, 256, gsmem>>>();

    const int fsmem = (QT + 4 * 64) * BPITCH * 2;     // 55296 B
    cudaFuncSetAttribute(flash_attn8,
                         cudaFuncAttributeMaxDynamicSharedMemorySize, fsmem);
    dim3 fgrid(T_SEQ / QT, BATCH * NH);
    flash_attn8<<<fgrid, 256, fsmem>>>(out);
}